// round 16
// baseline (speedup 1.0000x reference)
#include <cuda_runtime.h>
#include <cstdint>

// Radix2ModGroup: per 8-element group, quantize q = clip(round(x/0.05), +-255),
// keep the 12 largest-exponent set bits across the group's magnitudes
// (bit-planes scanned high->low; within a plane, lowest element index first),
// reconstruct kept magnitude * sign * 0.05.
//
// Bit-sliced, transpose-free (verified): mags packed as bytes in (lo, hi);
// C(b) via per-byte popc masks + 3-level branchless binary search for the
// critical plane t; rank-select of lowest-index plane-t bits via
// spread-multiply prefix sums. Magic-number (2^23) quant/dequant, no F2I/I2F.
//
// Configuration (R12 base, confirmed 3x at 20.96us bench):
//  - block 256, flat grid, 1 group/thread
//  - load: ld.global.v8.f32 — R16 adds L2::evict_last (input lines get
//    highest L2 retention priority; complements the .cs store policy on the
//    residency mechanism that drives the warm-loop time). Same request path
//    and L1 behavior as R12 — only the L2 replacement priority changes.
//  - store: 2x __stcs float4 (L2 evict-first) — verified R5: -7.5% warm loop.
// Warm-vs-cold lesson (R11, R14): st.cs.v8 / block=512 are cold-faster but
// warm-slower; the scored metric is the warm graph loop. Other dead ends:
// R3 MLP front-batch (2x), R6 persistent grid (+25%), R8 __ldcg (+8%).

__device__ __forceinline__ void ldg256_el(const float* p, float f[8])
{
    asm volatile("ld.global.L2::evict_last.v8.f32 {%0,%1,%2,%3,%4,%5,%6,%7}, [%8];"
                 : "=f"(f[0]), "=f"(f[1]), "=f"(f[2]), "=f"(f[3]),
                   "=f"(f[4]), "=f"(f[5]), "=f"(f[6]), "=f"(f[7])
                 : "l"(p));
}

__global__ void __launch_bounds__(256)
radix2_group_kernel(const float* __restrict__ x, float* __restrict__ out, int ngroups)
{
    int g = blockIdx.x * blockDim.x + threadIdx.x;
    if (g >= ngroups) return;

    const float MAGIC = 8388608.0f;   // 2^23, bit pattern 0x4B000000

    float xs[8];
    ldg256_el(x + (size_t)g * 8, xs);

    uint32_t sbits[8];
    uint32_t mb[8];
#pragma unroll
    for (int e = 0; e < 8; ++e) {
        sbits[e] = __float_as_uint(xs[e]) & 0x80000000u;
        // t = 2^23 + round_half_even(|x| * 20); low mantissa byte = magnitude
        float t = __fmaf_rn(fabsf(xs[e]), 20.0f, MAGIC);
        // clamp magnitude to 255 (saturate in the packed-bits domain)
        mb[e] = min(__float_as_uint(t), 0x4B0000FFu);
    }

    // pack 8 magnitude bytes -> lo (elems 0-3), hi (elems 4-7)
    uint32_t t01 = __byte_perm(mb[0], mb[1], 0x0040);
    uint32_t t23 = __byte_perm(mb[2], mb[3], 0x0040);
    uint32_t t45 = __byte_perm(mb[4], mb[5], 0x0040);
    uint32_t t67 = __byte_perm(mb[6], mb[7], 0x0040);
    uint32_t lo = __byte_perm(t01, t23, 0x5410);
    uint32_t hi = __byte_perm(t45, t67, 0x5410);

    uint32_t klo = lo, khi = hi;
    uint32_t ctot = __popc(lo) + __popc(hi);

    if (ctot > 12u) {
        // binary search for t = max b such that C(b) > 12,
        // where C(b) = #set bits in planes >= b (inclusive, monotone in b).
        uint32_t c4 = __popc(lo & 0xF0F0F0F0u) + __popc(hi & 0xF0F0F0F0u);   // C(4)
        bool g4 = c4 > 12u;
        uint32_t mA = g4 ? 0xC0C0C0C0u : 0xFCFCFCFCu;                        // C(6) / C(2)
        uint32_t c2 = __popc(lo & mA) + __popc(hi & mA);
        bool g2 = c2 > 12u;
        int bt3;
        uint32_t mB;
        if (g4) { if (g2) { bt3 = 7; mB = 0x80808080u; } else { bt3 = 5; mB = 0xE0E0E0E0u; } }
        else    { if (g2) { bt3 = 3; mB = 0xF8F8F8F8u; } else { bt3 = 1; mB = 0xFEFEFEFEu; } }
        uint32_t c1 = __popc(lo & mB) + __popc(hi & mB);                     // C(bt3)
        bool g1 = c1 > 12u;
        int t = g1 ? bt3 : bt3 - 1;
        // exclusive count above plane t = C(t+1)
        uint32_t exc = g1 ? (g2 ? (g4 ? 0u : c4) : c2) : c1;
        uint32_t r = 12u - exc;   // how many plane-t bits to keep (lowest elem idx first)

        // plane t in spread form: byte e, bit 0 = element e's bit t
        uint32_t sl = (lo >> t) & 0x01010101u;
        uint32_t sh = (hi >> t) & 0x01010101u;
        // inclusive ranks per element via multiply prefix-sum
        uint32_t rl = sl * 0x01010101u;
        uint32_t rh = sh * 0x01010101u + (rl >> 24) * 0x01010101u;
        // per-byte (rank <= r) flag in bit 7 (no cross-byte borrows: bytes small)
        uint32_t rb = r * 0x01010101u + 0x80808080u;
        uint32_t dl = (rb - rl) & 0x80808080u;
        uint32_t dh = (rb - rh) & 0x80808080u;
        uint32_t sell = sl & (dl >> 7);
        uint32_t selh = sh & (dh >> 7);

        uint32_t hm = ((0xFFu << (t + 1)) & 0xFFu) * 0x01010101u;  // planes > t fully kept
        klo = (lo & hm) | (sell << t);
        khi = (hi & hm) | (selh << t);
    }

    // dequantize: (float)kept * SF with sign from input (exact: 2^23 + kept
    // is exact; subtract is exact; single rounding in the SF multiply)
    float res[8];
#pragma unroll
    for (int e = 0; e < 8; ++e) {
        uint32_t src = (e < 4) ? klo : khi;
        uint32_t fb = __byte_perm(src, 0x4B000000u, 0x7440u | (uint32_t)(e & 3));
        float f = __uint_as_float(fb) - MAGIC;
        float o = f * 0.05f;
        res[e] = __uint_as_float(__float_as_uint(o) | sbits[e]);
    }

    float4* __restrict__ out4 = reinterpret_cast<float4*>(out) + (size_t)g * 2;
    __stcs(out4 + 0, make_float4(res[0], res[1], res[2], res[3]));
    __stcs(out4 + 1, make_float4(res[4], res[5], res[6], res[7]));
}

extern "C" void kernel_launch(void* const* d_in, const int* in_sizes, int n_in,
                              void* d_out, int out_size)
{
    const float* x = (const float*)d_in[0];
    float* out = (float*)d_out;
    int n = in_sizes[0];
    int ngroups = n >> 3;                 // 8 elements per group
    int threads = 256;
    int blocks = (ngroups + threads - 1) / threads;
    radix2_group_kernel<<<blocks, threads>>>(x, out, ngroups);
}